// round 7
// baseline (speedup 1.0000x reference)
#include <cuda_runtime.h>
#include <cuda_fp16.h>
#include <cstdint>
#include <cstring>

#define FH 38
#define FW 50
#define HW 1900
#define TAPS 15
#define NROIS 512
#define OUTDIM 490

#define S1 2
#define OCPAD1 256
#define OCPAD2 512
#define PROWS 3392            // padded rows: covers (i+7)*64+(j+7)+/-448 incl. guard tiles

// ---------------- scratch (no allocation allowed) ----------------
__device__ __half g_XP [PROWS * 2048];            // padded x, spatial-major, c contiguous
__device__ __half g_TP0[PROWS * 256];             // conv2 branch0 input (t0), padded
__device__ __half g_TP1[PROWS * 256];             // conv2 branch1 input (t1), padded
__device__ __half g_wt1[2 * TAPS * OCPAD1 * 2048];// conv1 weights [br][t][oc][c]
__device__ __half g_wt2[2 * TAPS * OCPAD2 * 256]; // conv2 weights
__device__ float  g_p1[2 * S1 * OCPAD1 * HW];     // conv1 partials [br][s][oc][p]
__device__ float  g_h0[OCPAD2 * HW];
__device__ float  g_h1[OCPAD2 * HW];
__device__ float  g_h [OUTDIM * HW];
__device__ float  g_flat[NROIS * OUTDIM];
__device__ float  g_fc1[NROIS * 2048];

// ---------------- PTX helpers ----------------
__device__ __forceinline__ uint32_t smem_u32(const void* p) {
    uint32_t a;
    asm("{ .reg .u64 t; cvta.to.shared.u64 t, %1; cvt.u32.u64 %0, t; }" : "=r"(a) : "l"(p));
    return a;
}
__device__ __forceinline__ void cp16(uint32_t dst, const __half* src) {
    asm volatile("cp.async.cg.shared.global [%0], [%1], 16;"
                 :: "r"(dst), "l"(__cvta_generic_to_global(src)));
}
__device__ __forceinline__ void cp_commit() {
    asm volatile("cp.async.commit_group;" ::: "memory");
}
template<int N> __device__ __forceinline__ void cp_wait() {
    asm volatile("cp.async.wait_group %0;" :: "n"(N) : "memory");
}
__device__ __forceinline__ void ldsm4(uint32_t* r, uint32_t addr) {
    asm volatile("ldmatrix.sync.aligned.m8n8.x4.shared.b16 {%0,%1,%2,%3}, [%4];"
        : "=r"(r[0]), "=r"(r[1]), "=r"(r[2]), "=r"(r[3]) : "r"(addr));
}
__device__ __forceinline__ void mma16(float* c, const uint32_t* a, const uint32_t* b) {
    asm volatile("mma.sync.aligned.m16n8k16.row.col.f32.f16.f16.f32 "
        "{%0,%1,%2,%3}, {%4,%5,%6,%7}, {%8,%9}, {%0,%1,%2,%3};"
        : "+f"(c[0]), "+f"(c[1]), "+f"(c[2]), "+f"(c[3])
        : "r"(a[0]), "r"(a[1]), "r"(a[2]), "r"(a[3]), "r"(b[0]), "r"(b[1]));
}
// FC path (f32x2)
__device__ __forceinline__ void ffma2u(unsigned long long &d, unsigned long long a, unsigned long long b) {
    asm("fma.rn.f32x2 %0, %1, %2, %0;" : "+l"(d) : "l"(a), "l"(b));
}
__device__ __forceinline__ unsigned long long bcast2(float x) {
    unsigned long long r;
    asm("mov.b64 %0, {%1, %1};" : "=l"(r) : "f"(x));
    return r;
}
__device__ __forceinline__ float2 unpack2(unsigned long long v) {
    float2 r;
    asm("mov.b64 {%0, %1}, %2;" : "=f"(r.x), "=f"(r.y) : "l"(v));
    return r;
}

// ---------------- prep: zero the padded buffers ----------------
__global__ void zero_fill(uint4* a, int na, uint4* b, int nb, uint4* c, int nc) {
    const int i = blockIdx.x * blockDim.x + threadIdx.x;
    const uint4 z = make_uint4(0, 0, 0, 0);
    if (i < na) a[i] = z;
    if (i < nb) b[i] = z;
    if (i < nc) c[i] = z;
}

// ---------------- prep: x [2048][1900] f32 -> XP [(i+7)*64+j+7][2048] half ----------------
__global__ __launch_bounds__(256) void xpose(const float* __restrict__ x, __half2* __restrict__ XP)
{
    __shared__ float s[64][65];
    const int c0 = blockIdx.x * 64, p0 = blockIdx.y * 64;
    const int tid = threadIdx.x;
    const int r = tid >> 2, q0 = (tid & 3) * 16;
#pragma unroll
    for (int q = 0; q < 16; q++) {
        const int p = p0 + q0 + q;
        s[r][q0 + q] = (p < HW) ? x[(size_t)(c0 + r) * HW + p] : 0.f;
    }
    __syncthreads();
#pragma unroll
    for (int k = 0; k < 8; k++) {
        const int widx = tid + k * 256;
        const int pl = widx >> 5, cp = widx & 31;
        const int p = p0 + pl;
        if (p < HW) {
            const int i = p / FW, j = p - i * FW;
            const int row = (i + 7) * 64 + j + 7;
            XP[(size_t)row * 1024 + (c0 >> 1) + cp] = __floats2half2_rn(s[2 * cp][pl], s[2 * cp + 1][pl]);
        }
    }
}

// ---------------- prep: w [oc][ic][15] f32 -> wt [t][ocpad][ic] half ----------------
__global__ __launch_bounds__(256) void wtrans(const float* __restrict__ w, __half* __restrict__ wt,
                                              int OC, int OCpad, int IC)
{
    __shared__ float s[128 * TAPS];
    const int m = blockIdx.x, c0 = blockIdx.y * 128;
    const int tid = threadIdx.x;
    if (m < OC) {
        const float* src = w + ((size_t)m * IC + c0) * TAPS;
        for (int i = tid; i < 128 * TAPS; i += 256) s[i] = src[i];
    } else {
        for (int i = tid; i < 128 * TAPS; i += 256) s[i] = 0.f;
    }
    __syncthreads();
    for (int i = tid; i < 128 * TAPS; i += 256) {
        const int t = i >> 7, ci = i & 127;
        wt[((size_t)t * OCpad + m) * IC + c0 + ci] = __float2half(s[ci * TAPS + t]);
    }
}

// ============ tap-decomposed fp16 GEMM conv: cp.async 3-stage + ldmatrix ============
// D[oc][p] = sum_t sum_c wt[t][oc][c] * P[qbase(p) + (t-7)*step][c]
#define NSTG 3
#define APITCH 80                 // 64B data + 16B pad: ldmatrix conflict-free
#define TILEB (128 * APITCH)      // 10240 B
#define STAGEB (2 * TILEB)
#define CONV_SMEM (NSTG * STAGEB) // 61440 B

__global__ __launch_bounds__(256, 1) void conv_mma(
    const __half* __restrict__ inB0, const __half* __restrict__ inB1,
    const __half* __restrict__ wA0,  const __half* __restrict__ wA1,
    float* __restrict__ out0, float* __restrict__ out1,
    int step0, int step1, int ICfull, int icChunks, int OCpad, int S)
{
    extern __shared__ __align__(16) char smem[];
    const int z = blockIdx.z;
    const int br = z / S, s = z % S;
    const __half* inB = br ? inB1 : inB0;
    const __half* wA  = br ? wA1  : wA0;
    float* out = (br ? out1 : out0) + (size_t)s * OCpad * HW;
    const int step = br ? step1 : step0;
    const int m0 = blockIdx.y * 128;
    const int p0 = blockIdx.x * 128;
    const int icOff = s * icChunks * 32;
    const int nit = TAPS * icChunks;

    const int tid = threadIdx.x;
    const int lane = tid & 31, wid = tid >> 5;
    const int wm = (wid >> 2) * 64, wn = (wid & 3) * 32;
    const int lg = lane >> 2, lt = lane & 3;
    const uint32_t sbase = smem_u32(smem);

    // loader: each thread owns one row (0..127) and one 32B half of the 64B chunk row
    const int lrow = tid >> 1, lseg = tid & 1;
    const int lp = p0 + lrow;
    const int li = lp / FW, lj = lp - li * FW;
    const int qbase = (li + 7) * 64 + lj + 7;
    const __half* aBase = wA + (size_t)(m0 + lrow) * ICfull + icOff + lseg * 16;
    const __half* bBase = inB + (size_t)qbase * ICfull + icOff + lseg * 16;
    const size_t aTapStride = (size_t)OCpad * ICfull;
    const long  bTapStride = (long)step * ICfull;
    const uint32_t aDstOff = (uint32_t)(lrow * APITCH + lseg * 32);
    const uint32_t bDstOff = aDstOff + TILEB;

    // ldmatrix lane addressing
    const uint32_t aLane = (uint32_t)((wm + (lane & 7) + ((lane >> 3) & 1) * 8) * APITCH + ((lane >> 4) & 1) * 16);
    const uint32_t bLane = (uint32_t)(TILEB + (wn + (lane & 7) + ((lane >> 4) & 1) * 8) * APITCH + ((lane >> 3) & 1) * 16);

    float acc[4][4][4];
#pragma unroll
    for (int mi = 0; mi < 4; mi++)
#pragma unroll
        for (int ni = 0; ni < 4; ni++)
#pragma unroll
            for (int q = 0; q < 4; q++) acc[mi][ni][q] = 0.f;

    int ti = 0, ci = 0;   // issue cursor: tap, channel-chunk
    auto issue = [&](int st) {
        const uint32_t buf = sbase + (st % NSTG) * STAGEB;
        const __half* aS = aBase + (size_t)ti * aTapStride + ci * 32;
        const __half* bS = bBase + (long)(ti - 7) * bTapStride + ci * 32;
        cp16(buf + aDstOff, aS); cp16(buf + aDstOff + 16, aS + 8);
        cp16(buf + bDstOff, bS); cp16(buf + bDstOff + 16, bS + 8);
        cp_commit();
        if (++ci == icChunks) { ci = 0; ++ti; }
    };

    issue(0); issue(1); issue(2);

    for (int it = 0; it < nit; ++it) {
        const int rem = nit - 1 - it;
        if (rem >= 2) cp_wait<2>();
        else if (rem == 1) cp_wait<1>();
        else cp_wait<0>();
        __syncthreads();

        const uint32_t buf = sbase + (it % NSTG) * STAGEB;
#pragma unroll
        for (int ks = 0; ks < 2; ks++) {
            uint32_t af[4][4], bf[4][2];
#pragma unroll
            for (int mi = 0; mi < 4; mi++)
                ldsm4(af[mi], buf + aLane + mi * (16 * APITCH) + ks * 32);
#pragma unroll
            for (int pr = 0; pr < 2; pr++) {
                uint32_t r[4];
                ldsm4(r, buf + bLane + pr * (16 * APITCH) + ks * 32);
                bf[pr * 2][0] = r[0]; bf[pr * 2][1] = r[1];
                bf[pr * 2 + 1][0] = r[2]; bf[pr * 2 + 1][1] = r[3];
            }
#pragma unroll
            for (int mi = 0; mi < 4; mi++)
#pragma unroll
                for (int ni = 0; ni < 4; ni++)
                    mma16(acc[mi][ni], af[mi], bf[ni]);
        }
        __syncthreads();
        if (it + 3 < nit) issue(it + 3);
    }

    // epilogue: D rows = oc, cols = real spatial p
#pragma unroll
    for (int mi = 0; mi < 4; mi++) {
        const int r0 = m0 + wm + mi * 16 + lg;
#pragma unroll
        for (int ni = 0; ni < 4; ni++) {
            const int cc = p0 + wn + ni * 8 + 2 * lt;
            if (cc < HW) {   // cc even, HW even -> pair safe
                *(float2*)&out[(size_t)r0 * HW + cc] = make_float2(acc[mi][ni][0], acc[mi][ni][1]);
                *(float2*)&out[(size_t)(r0 + 8) * HW + cc] = make_float2(acc[mi][ni][2], acc[mi][ni][3]);
            }
        }
    }
}

// ---------------- combine1: sum conv1 splits + bias -> padded half inputs for conv2 ----------------
__global__ __launch_bounds__(256) void combine1(const float* __restrict__ p1,
                                                const float* __restrict__ b0, const float* __restrict__ b1,
                                                __half2* __restrict__ TP0, __half2* __restrict__ TP1)
{
    __shared__ float s[64][65];
    const int b = blockIdx.z;
    const int m0 = blockIdx.x * 64, p0 = blockIdx.y * 64;
    const int tid = threadIdx.x;
    const float* base = p1 + (size_t)b * (S1 * OCPAD1 * HW);
    const int r = tid >> 2, q0 = (tid & 3) * 16;
#pragma unroll
    for (int q = 0; q < 16; q++) {
        const int p = p0 + q0 + q;
        s[r][q0 + q] = (p < HW)
            ? base[(size_t)(m0 + r) * HW + p] + base[(size_t)OCPAD1 * HW + (size_t)(m0 + r) * HW + p]
            : 0.f;
    }
    __syncthreads();
    const float* bias = b ? b1 : b0;
    __half2* TP = b ? TP1 : TP0;
#pragma unroll
    for (int k = 0; k < 8; k++) {
        const int widx = tid + k * 256;
        const int pl = widx >> 5, cp = widx & 31;
        const int p = p0 + pl;
        if (p < HW) {
            const int i = p / FW, j = p - i * FW;
            const int row = (i + 7) * 64 + j + 7;
            const float vx = s[2 * cp][pl] + bias[m0 + 2 * cp];
            const float vy = s[2 * cp + 1][pl] + bias[m0 + 2 * cp + 1];
            TP[(size_t)row * 128 + (m0 >> 1) + cp] = __floats2half2_rn(vx, vy);
        }
    }
}

// ---------------- combine2: h = relu(h0 + h1 + biases) ----------------
__global__ void combine2(const float4* __restrict__ h0, const float4* __restrict__ h1,
                         const float* __restrict__ bc, const float* __restrict__ brr,
                         float4* __restrict__ h)
{
    const int NP = HW / 4;
    const int idx = blockIdx.x * blockDim.x + threadIdx.x;
    if (idx >= OUTDIM * NP) return;
    const int m = idx / NP;
    const float4 a = h0[idx];
    const float4 b = h1[idx];
    const float bv = bc[m] + brr[m];
    float4 o;
    o.x = fmaxf(a.x + b.x + bv, 0.f);
    o.y = fmaxf(a.y + b.y + bv, 0.f);
    o.z = fmaxf(a.z + b.z + bv, 0.f);
    o.w = fmaxf(a.w + b.w + bv, 0.f);
    h[idx] = o;
}

// ---------------- ROI bilinear max pool ----------------
__global__ void roi_pool(const float* __restrict__ h, const float* __restrict__ rois,
                         float* __restrict__ flat)
{
    const int idx = blockIdx.x * blockDim.x + threadIdx.x;
    if (idx >= NROIS * OUTDIM) return;
    const int n  = idx / OUTDIM;
    const int ch = idx - n * OUTDIM;
    const int bin = ch / 10;
    const int bi  = bin / 7;
    const int bj  = bin - bi * 7;

    const float4 r = ((const float4*)rois)[n];
    const float xmin = (r.x * 0.0625f) / 50.f;
    const float ymin = (r.y * 0.0625f) / 38.f;
    const float xmax = (r.z * 0.0625f) / 50.f;
    const float ymax = (r.w * 0.0625f) / 38.f;
    const float stx = (xmax - xmin) / 7.f;
    const float sty = (ymax - ymin) / 7.f;

    const float* f = h + (size_t)ch * HW;
    float best = -3.4e38f;
#pragma unroll
    for (int ky = 0; ky < 2; ky++) {
        const float yy = (ymin + (float)(bi + ky) * sty) * 37.f;
        const float fy = floorf(yy);
        const float wy = yy - fy;
        const int y0 = (int)fminf(fmaxf(fy, 0.f), 37.f);
        const int y1 = (int)fminf(fmaxf(fy + 1.f, 0.f), 37.f);
#pragma unroll
        for (int kx = 0; kx < 2; kx++) {
            const float xx = (xmin + (float)(bj + kx) * stx) * 49.f;
            const float fx = floorf(xx);
            const float wx = xx - fx;
            const int x0 = (int)fminf(fmaxf(fx, 0.f), 49.f);
            const int x1 = (int)fminf(fmaxf(fx + 1.f, 0.f), 49.f);
            const float v00 = f[y0 * FW + x0];
            const float v01 = f[y0 * FW + x1];
            const float v10 = f[y1 * FW + x0];
            const float v11 = f[y1 * FW + x1];
            const float top = v00 + (v01 - v00) * wx;
            const float bot = v10 + (v11 - v10) * wx;
            const float val = top + (bot - top) * wy;
            best = fmaxf(best, val);
        }
    }
    flat[idx] = best;
}

// ---------------- GEMM: C[M,N] = A[M,K] * B[N,K]^T + bias (optional relu) ----------------
#define GBM 64
#define GBN 64
#define GBK 16

__global__ __launch_bounds__(128, 1) void gemm_tn(
    const float* __restrict__ A, const float* __restrict__ B,
    const float* __restrict__ bias, float* __restrict__ C,
    int M, int N, int K, int ldc, int relu)
{
    const int m0 = blockIdx.y * GBM;
    const int n0 = blockIdx.x * GBN;
    const int nit = (K + GBK - 1) / GBK;

    __shared__ __align__(16) float As[GBK][GBM + 4];
    __shared__ __align__(16) float Bs[GBK][GBN + 4];

    const int tid = threadIdx.x;
    const int tx = tid & 15;
    const int ty = tid >> 4;

    const int lr  = tid >> 1;
    const int lkq = (tid & 1) * 8;

    unsigned long long acc[8][2];
#pragma unroll
    for (int i = 0; i < 8; i++) { acc[i][0] = 0ull; acc[i][1] = 0ull; }

    for (int it = 0; it < nit; ++it) {
        const int k0 = it * GBK;
        {
            const int m = m0 + lr;
            const float* p = A + (size_t)m * K + k0 + lkq;
#pragma unroll
            for (int q = 0; q < 8; q++) {
                const int k = k0 + lkq + q;
                As[lkq + q][lr] = (m < M && k < K) ? __ldg(p + q) : 0.f;
            }
        }
        {
            const int nn = n0 + lr;
            const float* p = B + (size_t)nn * K + k0 + lkq;
#pragma unroll
            for (int q = 0; q < 8; q++) {
                const int k = k0 + lkq + q;
                Bs[lkq + q][lr] = (nn < N && k < K) ? __ldg(p + q) : 0.f;
            }
        }
        __syncthreads();
#pragma unroll
        for (int kk = 0; kk < GBK; kk++) {
            const float4 a0 = *(const float4*)&As[kk][ty * 8];
            const float4 a1 = *(const float4*)&As[kk][ty * 8 + 4];
            const ulonglong2 bv = *(const ulonglong2*)&Bs[kk][tx * 4];
            const float a[8] = { a0.x, a0.y, a0.z, a0.w, a1.x, a1.y, a1.z, a1.w };
#pragma unroll
            for (int mi = 0; mi < 8; mi++) {
                const unsigned long long av = bcast2(a[mi]);
                ffma2u(acc[mi][0], av, bv.x);
                ffma2u(acc[mi][1], av, bv.y);
            }
        }
        __syncthreads();
    }

#pragma unroll
    for (int mi = 0; mi < 8; mi++) {
        const int m = m0 + ty * 8 + mi;
        if (m >= M) continue;
        float* crow = C + (size_t)m * ldc;
#pragma unroll
        for (int nj = 0; nj < 2; nj++) {
            const float2 v = unpack2(acc[mi][nj]);
            const int n = n0 + tx * 4 + nj * 2;
            if (n < N) {
                float o = v.x + bias[n];
                if (relu) o = o > 0.f ? o : 0.f;
                crow[n] = o;
            }
            if (n + 1 < N) {
                float o = v.y + bias[n + 1];
                if (relu) o = o > 0.f ? o : 0.f;
                crow[n + 1] = o;
            }
        }
    }
}

// ---------------- launch ----------------
extern "C" void kernel_launch(void* const* d_in, const int* in_sizes, int n_in,
                              void* d_out, int out_size)
{
    const float* x          = (const float*)d_in[0];
    const float* rois       = (const float*)d_in[1];
    const float* w_col_max  = (const float*)d_in[2];
    const float* b_col_max  = (const float*)d_in[3];
    const float* w_col      = (const float*)d_in[4];
    const float* b_col      = (const float*)d_in[5];
    const float* w_row_max  = (const float*)d_in[6];
    const float* b_row_max  = (const float*)d_in[7];
    const float* w_row      = (const float*)d_in[8];
    const float* b_row      = (const float*)d_in[9];
    const float* w_fc1      = (const float*)d_in[10];
    const float* b_fc1      = (const float*)d_in[11];
    const float* w_score    = (const float*)d_in[12];
    const float* b_score    = (const float*)d_in[13];
    const float* w_loc      = (const float*)d_in[14];
    const float* b_loc      = (const float*)d_in[15];
    float* out = (float*)d_out;

    __half *XP, *TP0, *TP1, *wt1, *wt2;
    float *p1, *h0, *h1, *h, *flat, *fc1;
    cudaGetSymbolAddress((void**)&XP,   g_XP);
    cudaGetSymbolAddress((void**)&TP0,  g_TP0);
    cudaGetSymbolAddress((void**)&TP1,  g_TP1);
    cudaGetSymbolAddress((void**)&wt1,  g_wt1);
    cudaGetSymbolAddress((void**)&wt2,  g_wt2);
    cudaGetSymbolAddress((void**)&p1,   g_p1);
    cudaGetSymbolAddress((void**)&h0,   g_h0);
    cudaGetSymbolAddress((void**)&h1,   g_h1);
    cudaGetSymbolAddress((void**)&h,    g_h);
    cudaGetSymbolAddress((void**)&flat, g_flat);
    cudaGetSymbolAddress((void**)&fc1,  g_fc1);

    cudaFuncSetAttribute(conv_mma, cudaFuncAttributeMaxDynamicSharedMemorySize, CONV_SMEM);

    // prep: zero padded buffers (pads must be zero; valid regions overwritten below)
    {
        const int na = PROWS * 2048 * 2 / 16;   // XP bytes/16
        const int nb = PROWS * 256  * 2 / 16;   // TP bytes/16
        zero_fill<<<(na + 255) / 256, 256>>>((uint4*)XP, na, (uint4*)TP0, nb, (uint4*)TP1, nb);
    }
    // transpose x -> XP
    xpose<<<dim3(2048 / 64, (HW + 63) / 64), 256>>>(x, (__half2*)XP);
    // weights -> [t][oc][c] half
    wtrans<<<dim3(OCPAD1, 2048 / 128), 256>>>(w_col_max, wt1, 256, OCPAD1, 2048);
    wtrans<<<dim3(OCPAD1, 2048 / 128), 256>>>(w_row_max, wt1 + (size_t)TAPS * OCPAD1 * 2048, 256, OCPAD1, 2048);
    wtrans<<<dim3(OCPAD2, 256 / 128), 256>>>(w_col, wt2, OUTDIM, OCPAD2, 256);
    wtrans<<<dim3(OCPAD2, 256 / 128), 256>>>(w_row, wt2 + (size_t)TAPS * OCPAD2 * 256, OUTDIM, OCPAD2, 256);

    // conv1: branch0 = w_col_max (15x1, H-shift step 64), branch1 = w_row_max (1x15, W-shift step 1)
    {
        dim3 grid((HW + 127) / 128, OCPAD1 / 128, 2 * S1);   // 15 x 2 x 4 = 120
        conv_mma<<<grid, 256, CONV_SMEM>>>(
            XP, XP,
            wt1, wt1 + (size_t)TAPS * OCPAD1 * 2048,
            p1, p1 + (size_t)S1 * OCPAD1 * HW,
            64, 1, 2048, 2048 / 32 / S1, OCPAD1, S1);
    }
    // combine1: sum splits + bias -> TP0/TP1 (padded half)
    combine1<<<dim3(OCPAD1 / 64, (HW + 63) / 64, 2), 256>>>(p1, b_col_max, b_row_max,
                                                            (__half2*)TP0, (__half2*)TP1);
    // conv2: branch0 = TP0 with w_col (1x15, W step 1), branch1 = TP1 with w_row (15x1, H step 64)
    {
        dim3 grid((HW + 127) / 128, OCPAD2 / 128, 2);        // 15 x 4 x 2 = 120
        conv_mma<<<grid, 256, CONV_SMEM>>>(
            TP0, TP1,
            wt2, wt2 + (size_t)TAPS * OCPAD2 * 256,
            h0, h1,
            1, 64, 256, 256 / 32, OCPAD2, 1);
    }
    // h = relu(h0 + h1 + b_col + b_row)
    {
        const int n = OUTDIM * (HW / 4);
        combine2<<<(n + 255) / 256, 256>>>((const float4*)h0, (const float4*)h1, b_col, b_row, (float4*)h);
    }
    // ROI pool -> flat [512, 490]
    {
        const int n = NROIS * OUTDIM;
        roi_pool<<<(n + 255) / 256, 256>>>(h, rois, flat);
    }
    // fc1 = relu(flat @ w_fc1^T + b_fc1)   [512, 2048]
    {
        dim3 grid(2048 / GBN, NROIS / GBM);
        gemm_tn<<<grid, 128>>>(flat, w_fc1, b_fc1, fc1, NROIS, 2048, OUTDIM, 2048, 1);
    }
    // roi_cls_locs = fc1 @ w_loc^T + b_loc   [512, 324]
    {
        dim3 grid((324 + GBN - 1) / GBN, NROIS / GBM);
        gemm_tn<<<grid, 128>>>(fc1, w_loc, b_loc, out, NROIS, 324, 2048, 324, 0);
    }
    // roi_scores = fc1 @ w_score^T + b_score [512, 81]
    {
        dim3 grid((81 + GBN - 1) / GBN, NROIS / GBM);
        gemm_tn<<<grid, 128>>>(fc1, w_score, b_score, out + NROIS * 324, NROIS, 81, 2048, 81, 0);
    }
}

// round 8
// speedup vs baseline: 1.0423x; 1.0423x over previous
#include <cuda_runtime.h>
#include <cuda_fp16.h>
#include <cstdint>
#include <cstring>

#define FH 38
#define FW 50
#define HW 1900
#define TAPS 15
#define NROIS 512
#define OUTDIM 490

#define S1 4
#define S2 2
#define OCPAD1 256
#define OCPAD2 512
#define PROWS 3392

// ---------------- scratch ----------------
__device__ __half g_XP [PROWS * 2048];
__device__ __half g_TP0[PROWS * 256];
__device__ __half g_TP1[PROWS * 256];
__device__ __half g_wt1[2 * TAPS * OCPAD1 * 2048];
__device__ __half g_wt2[2 * TAPS * OCPAD2 * 256];
__device__ float  g_p1[2 * S1 * OCPAD1 * HW];
__device__ float  g_h0[S2 * OCPAD2 * HW];
__device__ float  g_h1[S2 * OCPAD2 * HW];
__device__ float  g_h [OUTDIM * HW];
__device__ float  g_flat[NROIS * OUTDIM];
__device__ float  g_fc1[NROIS * 2048];

// ---------------- PTX helpers ----------------
__device__ __forceinline__ uint32_t smem_u32(const void* p) {
    uint32_t a;
    asm("{ .reg .u64 t; cvta.to.shared.u64 t, %1; cvt.u32.u64 %0, t; }" : "=r"(a) : "l"(p));
    return a;
}
__device__ __forceinline__ void cp16(uint32_t dst, const __half* src) {
    asm volatile("cp.async.cg.shared.global [%0], [%1], 16;"
                 :: "r"(dst), "l"(__cvta_generic_to_global(src)));
}
__device__ __forceinline__ void cp_commit() {
    asm volatile("cp.async.commit_group;" ::: "memory");
}
template<int N> __device__ __forceinline__ void cp_wait() {
    asm volatile("cp.async.wait_group %0;" :: "n"(N) : "memory");
}
__device__ __forceinline__ void ldsm4(uint32_t* r, uint32_t addr) {
    asm volatile("ldmatrix.sync.aligned.m8n8.x4.shared.b16 {%0,%1,%2,%3}, [%4];"
        : "=r"(r[0]), "=r"(r[1]), "=r"(r[2]), "=r"(r[3]) : "r"(addr));
}
__device__ __forceinline__ void mma16(float* c, const uint32_t* a, const uint32_t* b) {
    asm volatile("mma.sync.aligned.m16n8k16.row.col.f32.f16.f16.f32 "
        "{%0,%1,%2,%3}, {%4,%5,%6,%7}, {%8,%9}, {%0,%1,%2,%3};"
        : "+f"(c[0]), "+f"(c[1]), "+f"(c[2]), "+f"(c[3])
        : "r"(a[0]), "r"(a[1]), "r"(a[2]), "r"(a[3]), "r"(b[0]), "r"(b[1]));
}
__device__ __forceinline__ void ffma2u(unsigned long long &d, unsigned long long a, unsigned long long b) {
    asm("fma.rn.f32x2 %0, %1, %2, %0;" : "+l"(d) : "l"(a), "l"(b));
}
__device__ __forceinline__ unsigned long long bcast2(float x) {
    unsigned long long r;
    asm("mov.b64 %0, {%1, %1};" : "=l"(r) : "f"(x));
    return r;
}
__device__ __forceinline__ float2 unpack2(unsigned long long v) {
    float2 r;
    asm("mov.b64 {%0, %1}, %2;" : "=f"(r.x), "=f"(r.y) : "l"(v));
    return r;
}

// ---------------- prep kernels ----------------
__global__ void zero_fill(uint4* a, int na, uint4* b, int nb, uint4* c, int nc) {
    const int i = blockIdx.x * blockDim.x + threadIdx.x;
    const uint4 z = make_uint4(0, 0, 0, 0);
    if (i < na) a[i] = z;
    if (i < nb) b[i] = z;
    if (i < nc) c[i] = z;
}

__global__ __launch_bounds__(256) void xpose(const float* __restrict__ x, __half2* __restrict__ XP)
{
    __shared__ float s[64][65];
    const int c0 = blockIdx.x * 64, p0 = blockIdx.y * 64;
    const int tid = threadIdx.x;
    const int r = tid >> 2, q0 = (tid & 3) * 16;
#pragma unroll
    for (int q = 0; q < 16; q++) {
        const int p = p0 + q0 + q;
        s[r][q0 + q] = (p < HW) ? x[(size_t)(c0 + r) * HW + p] : 0.f;
    }
    __syncthreads();
#pragma unroll
    for (int k = 0; k < 8; k++) {
        const int widx = tid + k * 256;
        const int pl = widx >> 5, cp = widx & 31;
        const int p = p0 + pl;
        if (p < HW) {
            const int i = p / FW, j = p - i * FW;
            const int row = (i + 7) * 64 + j + 7;
            XP[(size_t)row * 1024 + (c0 >> 1) + cp] = __floats2half2_rn(s[2 * cp][pl], s[2 * cp + 1][pl]);
        }
    }
}

__global__ __launch_bounds__(256) void wtrans(const float* __restrict__ w, __half* __restrict__ wt,
                                              int OC, int OCpad, int IC)
{
    __shared__ float s[128 * TAPS];
    const int m = blockIdx.x, c0 = blockIdx.y * 128;
    const int tid = threadIdx.x;
    if (m < OC) {
        const float* src = w + ((size_t)m * IC + c0) * TAPS;
        for (int i = tid; i < 128 * TAPS; i += 256) s[i] = src[i];
    } else {
        for (int i = tid; i < 128 * TAPS; i += 256) s[i] = 0.f;
    }
    __syncthreads();
    for (int i = tid; i < 128 * TAPS; i += 256) {
        const int t = i >> 7, ci = i & 127;
        wt[((size_t)t * OCpad + m) * IC + c0 + ci] = __float2half(s[ci * TAPS + t]);
    }
}

// ============ tap-decomposed fp16 conv, BM=128 x BN=256 ============
#define NSTG 3
#define APITCH 80
#define ABUF (128 * APITCH)        // 10240
#define BBUF (256 * APITCH)        // 20480
#define STAGEB (ABUF + BBUF)       // 30720
#define CONV_SMEM (NSTG * STAGEB)  // 92160

__global__ __launch_bounds__(256, 1) void conv_mma(
    const __half* __restrict__ inB0, const __half* __restrict__ inB1,
    const __half* __restrict__ wA0,  const __half* __restrict__ wA1,
    float* __restrict__ out0, float* __restrict__ out1,
    int step0, int step1, int ICfull, int icChunks, int OCpad, int S)
{
    extern __shared__ __align__(16) char smem[];
    const int z = blockIdx.z;
    const int br = z / S, s = z % S;
    const __half* inB = br ? inB1 : inB0;
    const __half* wA  = br ? wA1  : wA0;
    float* out = (br ? out1 : out0) + (size_t)s * OCpad * HW;
    const int step = br ? step1 : step0;
    const int m0 = blockIdx.y * 128;
    const int p0 = blockIdx.x * 256;
    const int icOff = s * icChunks * 32;
    const int nit = TAPS * icChunks;

    const int tid = threadIdx.x;
    const int lane = tid & 31, wid = tid >> 5;
    const int wm = (wid >> 2) * 64, wn = (wid & 3) * 64;
    const int lg = lane >> 2, lt = lane & 3;
    const uint32_t sbase = smem_u32(smem);

    // A loader: 2 threads per row (128 rows); B loader: 1 thread per row (256 rows)
    const int arow = tid >> 1, aseg = tid & 1;
    int lp = p0 + tid; if (lp > HW - 1) lp = HW - 1;
    const int li = lp / FW, lj = lp - li * FW;
    const int qbase = (li + 7) * 64 + lj + 7;
    const __half* aBase = wA + (size_t)(m0 + arow) * ICfull + icOff + aseg * 16;
    const __half* bBase = inB + (size_t)qbase * ICfull + icOff;
    const size_t aTapStride = (size_t)OCpad * ICfull;
    const long  bTapStride = (long)step * ICfull;
    const uint32_t aDstOff = (uint32_t)(arow * APITCH + aseg * 32);
    const uint32_t bDstOff = (uint32_t)(ABUF + tid * APITCH);

    const uint32_t aLane = (uint32_t)((wm + (lane & 7) + ((lane >> 3) & 1) * 8) * APITCH + ((lane >> 4) & 1) * 16);
    const uint32_t bLane0 = (uint32_t)(ABUF + (wn + (lane & 7) + ((lane >> 4) & 1) * 8) * APITCH + ((lane >> 3) & 1) * 16);

    float acc[4][8][4];
#pragma unroll
    for (int mi = 0; mi < 4; mi++)
#pragma unroll
        for (int ni = 0; ni < 8; ni++)
#pragma unroll
            for (int q = 0; q < 4; q++) acc[mi][ni][q] = 0.f;

    int ti = 0, ci = 0;
    auto issue = [&](int st) {
        const uint32_t buf = sbase + (st % NSTG) * STAGEB;
        const __half* aS = aBase + (size_t)ti * aTapStride + ci * 32;
        const __half* bS = bBase + (long)(ti - 7) * bTapStride + ci * 32;
        cp16(buf + aDstOff, aS); cp16(buf + aDstOff + 16, aS + 8);
        const uint32_t bd = buf + bDstOff;
        cp16(bd, bS); cp16(bd + 16, bS + 8); cp16(bd + 32, bS + 16); cp16(bd + 48, bS + 24);
        cp_commit();
        if (++ci == icChunks) { ci = 0; ++ti; }
    };

    issue(0); issue(1); issue(2);

    for (int it = 0; it < nit; ++it) {
        const int rem = nit - 1 - it;
        if (rem >= 2) cp_wait<2>();
        else if (rem == 1) cp_wait<1>();
        else cp_wait<0>();
        __syncthreads();

        const uint32_t buf = sbase + (it % NSTG) * STAGEB;
#pragma unroll
        for (int ks = 0; ks < 2; ks++) {
            uint32_t af[4][4], bf[8][2];
#pragma unroll
            for (int mi = 0; mi < 4; mi++)
                ldsm4(af[mi], buf + aLane + mi * (16 * APITCH) + ks * 32);
#pragma unroll
            for (int pr = 0; pr < 4; pr++) {
                uint32_t r[4];
                ldsm4(r, buf + bLane0 + pr * (16 * APITCH) + ks * 32);
                bf[pr * 2][0] = r[0]; bf[pr * 2][1] = r[1];
                bf[pr * 2 + 1][0] = r[2]; bf[pr * 2 + 1][1] = r[3];
            }
#pragma unroll
            for (int mi = 0; mi < 4; mi++)
#pragma unroll
                for (int ni = 0; ni < 8; ni++)
                    mma16(acc[mi][ni], af[mi], bf[ni]);
        }
        __syncthreads();
        if (it + 3 < nit) issue(it + 3);
    }

#pragma unroll
    for (int mi = 0; mi < 4; mi++) {
        const int r0 = m0 + wm + mi * 16 + lg;
#pragma unroll
        for (int ni = 0; ni < 8; ni++) {
            const int cc = p0 + wn + ni * 8 + 2 * lt;
            if (cc < HW) {
                *(float2*)&out[(size_t)r0 * HW + cc] = make_float2(acc[mi][ni][0], acc[mi][ni][1]);
                *(float2*)&out[(size_t)(r0 + 8) * HW + cc] = make_float2(acc[mi][ni][2], acc[mi][ni][3]);
            }
        }
    }
}

// ---------------- combine1: sum S1 splits + bias -> padded half ----------------
__global__ __launch_bounds__(256) void combine1(const float* __restrict__ p1,
                                                const float* __restrict__ b0, const float* __restrict__ b1,
                                                __half2* __restrict__ TP0, __half2* __restrict__ TP1)
{
    __shared__ float s[64][65];
    const int b = blockIdx.z;
    const int m0 = blockIdx.x * 64, p0 = blockIdx.y * 64;
    const int tid = threadIdx.x;
    const float* base = p1 + (size_t)b * (S1 * OCPAD1 * HW);
    const int r = tid >> 2, q0 = (tid & 3) * 16;
#pragma unroll
    for (int q = 0; q < 16; q++) {
        const int p = p0 + q0 + q;
        float v = 0.f;
        if (p < HW) {
            const float* src = base + (size_t)(m0 + r) * HW + p;
#pragma unroll
            for (int ss = 0; ss < S1; ss++) v += src[(size_t)ss * OCPAD1 * HW];
        }
        s[r][q0 + q] = v;
    }
    __syncthreads();
    const float* bias = b ? b1 : b0;
    __half2* TP = b ? TP1 : TP0;
#pragma unroll
    for (int k = 0; k < 8; k++) {
        const int widx = tid + k * 256;
        const int pl = widx >> 5, cp = widx & 31;
        const int p = p0 + pl;
        if (p < HW) {
            const int i = p / FW, j = p - i * FW;
            const int row = (i + 7) * 64 + j + 7;
            const float vx = s[2 * cp][pl] + bias[m0 + 2 * cp];
            const float vy = s[2 * cp + 1][pl] + bias[m0 + 2 * cp + 1];
            TP[(size_t)row * 128 + (m0 >> 1) + cp] = __floats2half2_rn(vx, vy);
        }
    }
}

// ---------------- combine2: relu(sum S2 partials both branches + biases) ----------------
__global__ void combine2(const float* __restrict__ h0, const float* __restrict__ h1,
                         const float* __restrict__ bc, const float* __restrict__ brr,
                         float4* __restrict__ h)
{
    const int NP = HW / 4;
    const int idx = blockIdx.x * blockDim.x + threadIdx.x;
    if (idx >= OUTDIM * NP) return;
    const int m = idx / NP;
    const size_t off = (size_t)idx * 4 + (size_t)m * 0;   // idx*4 indexes [m][p] since NP*4=HW
    float4 a = make_float4(0.f, 0.f, 0.f, 0.f);
#pragma unroll
    for (int ss = 0; ss < S2; ss++) {
        const float4 v0 = *(const float4*)&h0[(size_t)ss * OCPAD2 * HW + off];
        const float4 v1 = *(const float4*)&h1[(size_t)ss * OCPAD2 * HW + off];
        a.x += v0.x + v1.x; a.y += v0.y + v1.y; a.z += v0.z + v1.z; a.w += v0.w + v1.w;
    }
    const float bv = bc[m] + brr[m];
    h[idx] = make_float4(fmaxf(a.x + bv, 0.f), fmaxf(a.y + bv, 0.f),
                         fmaxf(a.z + bv, 0.f), fmaxf(a.w + bv, 0.f));
}

// ---------------- ROI bilinear max pool ----------------
__global__ void roi_pool(const float* __restrict__ h, const float* __restrict__ rois,
                         float* __restrict__ flat)
{
    const int idx = blockIdx.x * blockDim.x + threadIdx.x;
    if (idx >= NROIS * OUTDIM) return;
    const int n  = idx / OUTDIM;
    const int ch = idx - n * OUTDIM;
    const int bin = ch / 10;
    const int bi  = bin / 7;
    const int bj  = bin - bi * 7;

    const float4 r = ((const float4*)rois)[n];
    const float xmin = (r.x * 0.0625f) / 50.f;
    const float ymin = (r.y * 0.0625f) / 38.f;
    const float xmax = (r.z * 0.0625f) / 50.f;
    const float ymax = (r.w * 0.0625f) / 38.f;
    const float stx = (xmax - xmin) / 7.f;
    const float sty = (ymax - ymin) / 7.f;

    const float* f = h + (size_t)ch * HW;
    float best = -3.4e38f;
#pragma unroll
    for (int ky = 0; ky < 2; ky++) {
        const float yy = (ymin + (float)(bi + ky) * sty) * 37.f;
        const float fy = floorf(yy);
        const float wy = yy - fy;
        const int y0 = (int)fminf(fmaxf(fy, 0.f), 37.f);
        const int y1 = (int)fminf(fmaxf(fy + 1.f, 0.f), 37.f);
#pragma unroll
        for (int kx = 0; kx < 2; kx++) {
            const float xx = (xmin + (float)(bj + kx) * stx) * 49.f;
            const float fx = floorf(xx);
            const float wx = xx - fx;
            const int x0 = (int)fminf(fmaxf(fx, 0.f), 49.f);
            const int x1 = (int)fminf(fmaxf(fx + 1.f, 0.f), 49.f);
            const float v00 = f[y0 * FW + x0];
            const float v01 = f[y0 * FW + x1];
            const float v10 = f[y1 * FW + x0];
            const float v11 = f[y1 * FW + x1];
            const float top = v00 + (v01 - v00) * wx;
            const float bot = v10 + (v11 - v10) * wx;
            const float val = top + (bot - top) * wy;
            best = fmaxf(best, val);
        }
    }
    flat[idx] = best;
}

// ---------------- GEMM: C = A * B^T + bias ----------------
#define GBM 64
#define GBN 64
#define GBK 16

__global__ __launch_bounds__(128, 1) void gemm_tn(
    const float* __restrict__ A, const float* __restrict__ B,
    const float* __restrict__ bias, float* __restrict__ C,
    int M, int N, int K, int ldc, int relu)
{
    const int m0 = blockIdx.y * GBM;
    const int n0 = blockIdx.x * GBN;
    const int nit = (K + GBK - 1) / GBK;

    __shared__ __align__(16) float As[GBK][GBM + 4];
    __shared__ __align__(16) float Bs[GBK][GBN + 4];

    const int tid = threadIdx.x;
    const int tx = tid & 15;
    const int ty = tid >> 4;
    const int lr  = tid >> 1;
    const int lkq = (tid & 1) * 8;

    unsigned long long acc[8][2];
#pragma unroll
    for (int i = 0; i < 8; i++) { acc[i][0] = 0ull; acc[i][1] = 0ull; }

    for (int it = 0; it < nit; ++it) {
        const int k0 = it * GBK;
        {
            const int m = m0 + lr;
            const float* p = A + (size_t)m * K + k0 + lkq;
#pragma unroll
            for (int q = 0; q < 8; q++) {
                const int k = k0 + lkq + q;
                As[lkq + q][lr] = (m < M && k < K) ? __ldg(p + q) : 0.f;
            }
        }
        {
            const int nn = n0 + lr;
            const float* p = B + (size_t)nn * K + k0 + lkq;
#pragma unroll
            for (int q = 0; q < 8; q++) {
                const int k = k0 + lkq + q;
                Bs[lkq + q][lr] = (nn < N && k < K) ? __ldg(p + q) : 0.f;
            }
        }
        __syncthreads();
#pragma unroll
        for (int kk = 0; kk < GBK; kk++) {
            const float4 a0 = *(const float4*)&As[kk][ty * 8];
            const float4 a1 = *(const float4*)&As[kk][ty * 8 + 4];
            const ulonglong2 bv = *(const ulonglong2*)&Bs[kk][tx * 4];
            const float a[8] = { a0.x, a0.y, a0.z, a0.w, a1.x, a1.y, a1.z, a1.w };
#pragma unroll
            for (int mi = 0; mi < 8; mi++) {
                const unsigned long long av = bcast2(a[mi]);
                ffma2u(acc[mi][0], av, bv.x);
                ffma2u(acc[mi][1], av, bv.y);
            }
        }
        __syncthreads();
    }

#pragma unroll
    for (int mi = 0; mi < 8; mi++) {
        const int m = m0 + ty * 8 + mi;
        if (m >= M) continue;
        float* crow = C + (size_t)m * ldc;
#pragma unroll
        for (int nj = 0; nj < 2; nj++) {
            const float2 v = unpack2(acc[mi][nj]);
            const int n = n0 + tx * 4 + nj * 2;
            if (n < N) {
                float o = v.x + bias[n];
                if (relu) o = o > 0.f ? o : 0.f;
                crow[n] = o;
            }
            if (n + 1 < N) {
                float o = v.y + bias[n + 1];
                if (relu) o = o > 0.f ? o : 0.f;
                crow[n + 1] = o;
            }
        }
    }
}

// ---------------- launch ----------------
extern "C" void kernel_launch(void* const* d_in, const int* in_sizes, int n_in,
                              void* d_out, int out_size)
{
    const float* x          = (const float*)d_in[0];
    const float* rois       = (const float*)d_in[1];
    const float* w_col_max  = (const float*)d_in[2];
    const float* b_col_max  = (const float*)d_in[3];
    const float* w_col      = (const float*)d_in[4];
    const float* b_col      = (const float*)d_in[5];
    const float* w_row_max  = (const float*)d_in[6];
    const float* b_row_max  = (const float*)d_in[7];
    const float* w_row      = (const float*)d_in[8];
    const float* b_row      = (const float*)d_in[9];
    const float* w_fc1      = (const float*)d_in[10];
    const float* b_fc1      = (const float*)d_in[11];
    const float* w_score    = (const float*)d_in[12];
    const float* b_score    = (const float*)d_in[13];
    const float* w_loc      = (const float*)d_in[14];
    const float* b_loc      = (const float*)d_in[15];
    float* out = (float*)d_out;

    __half *XP, *TP0, *TP1, *wt1, *wt2;
    float *p1, *h0, *h1, *h, *flat, *fc1;
    cudaGetSymbolAddress((void**)&XP,   g_XP);
    cudaGetSymbolAddress((void**)&TP0,  g_TP0);
    cudaGetSymbolAddress((void**)&TP1,  g_TP1);
    cudaGetSymbolAddress((void**)&wt1,  g_wt1);
    cudaGetSymbolAddress((void**)&wt2,  g_wt2);
    cudaGetSymbolAddress((void**)&p1,   g_p1);
    cudaGetSymbolAddress((void**)&h0,   g_h0);
    cudaGetSymbolAddress((void**)&h1,   g_h1);
    cudaGetSymbolAddress((void**)&h,    g_h);
    cudaGetSymbolAddress((void**)&flat, g_flat);
    cudaGetSymbolAddress((void**)&fc1,  g_fc1);

    cudaFuncSetAttribute(conv_mma, cudaFuncAttributeMaxDynamicSharedMemorySize, CONV_SMEM);

    {
        const int na = PROWS * 2048 * 2 / 16;
        const int nb = PROWS * 256  * 2 / 16;
        zero_fill<<<(na + 255) / 256, 256>>>((uint4*)XP, na, (uint4*)TP0, nb, (uint4*)TP1, nb);
    }
    xpose<<<dim3(2048 / 64, (HW + 63) / 64), 256>>>(x, (__half2*)XP);
    wtrans<<<dim3(OCPAD1, 2048 / 128), 256>>>(w_col_max, wt1, 256, OCPAD1, 2048);
    wtrans<<<dim3(OCPAD1, 2048 / 128), 256>>>(w_row_max, wt1 + (size_t)TAPS * OCPAD1 * 2048, 256, OCPAD1, 2048);
    wtrans<<<dim3(OCPAD2, 256 / 128), 256>>>(w_col, wt2, OUTDIM, OCPAD2, 256);
    wtrans<<<dim3(OCPAD2, 256 / 128), 256>>>(w_row, wt2 + (size_t)TAPS * OCPAD2 * 256, OUTDIM, OCPAD2, 256);

    // conv1: BN=256 tiles; 8 x 2 x (2*S1=8) = 128 CTAs
    {
        dim3 grid((HW + 255) / 256, OCPAD1 / 128, 2 * S1);
        conv_mma<<<grid, 256, CONV_SMEM>>>(
            XP, XP,
            wt1, wt1 + (size_t)TAPS * OCPAD1 * 2048,
            p1, p1 + (size_t)S1 * OCPAD1 * HW,
            64, 1, 2048, 2048 / 32 / S1, OCPAD1, S1);
    }
    combine1<<<dim3(OCPAD1 / 64, (HW + 63) / 64, 2), 256>>>(p1, b_col_max, b_row_max,
                                                            (__half2*)TP0, (__half2*)TP1);
    // conv2: 8 x 4 x (2*S2=4) = 128 CTAs
    {
        dim3 grid((HW + 255) / 256, OCPAD2 / 128, 2 * S2);
        conv_mma<<<grid, 256, CONV_SMEM>>>(
            TP0, TP1,
            wt2, wt2 + (size_t)TAPS * OCPAD2 * 256,
            h0, h1,
            1, 64, 256, 256 / 32 / S2, OCPAD2, S2);
    }
    {
        const int n = OUTDIM * (HW / 4);
        combine2<<<(n + 255) / 256, 256>>>(h0, h1, b_col, b_row, (float4*)h);
    }
    {
        const int n = NROIS * OUTDIM;
        roi_pool<<<(n + 255) / 256, 256>>>(h, rois, flat);
    }
    {
        dim3 grid(2048 / GBN, NROIS / GBM);
        gemm_tn<<<grid, 128>>>(flat, w_fc1, b_fc1, fc1, NROIS, 2048, OUTDIM, 2048, 1);
    }
    {
        dim3 grid((324 + GBN - 1) / GBN, NROIS / GBM);
        gemm_tn<<<grid, 128>>>(fc1, w_loc, b_loc, out, NROIS, 324, 2048, 324, 0);
    }
    {
        dim3 grid((81 + GBN - 1) / GBN, NROIS / GBM);
        gemm_tn<<<grid, 128>>>(fc1, w_score, b_score, out + NROIS * 324, NROIS, 81, 2048, 81, 0);
    }
}

// round 9
// speedup vs baseline: 1.1661x; 1.1188x over previous
#include <cuda_runtime.h>
#include <cuda_fp16.h>
#include <cstdint>
#include <cstring>

#define FH 38
#define FW 50
#define HW 1900
#define TAPS 15
#define NROIS 512
#define OUTDIM 490
#define S1 4
#define S2 2
#define OCPAD1 256
#define OCPAD2 512
#define PROWS 4096

// ---------------- scratch ----------------
__device__ __half g_XPa[PROWS * 2048];   // i-major: row=(i+7)*64+j+7, enum p=i*50+j
__device__ __half g_XPb[PROWS * 2048];   // j-major: row=(j+7)*64+i+7, enum e=j*38+i
__device__ __half g_TP0[PROWS * 256];    // t0, i-major (conv2 br0, W-shift)
__device__ __half g_TP1[PROWS * 256];    // t1, j-major (conv2 br1, H-shift)
__device__ __half g_wt1[2 * TAPS * OCPAD1 * 2048];
__device__ __half g_wt2[2 * TAPS * OCPAD2 * 256];
__device__ float  g_p1[2 * S1 * OCPAD1 * HW];
__device__ float  g_h0[S2 * OCPAD2 * HW];
__device__ float  g_h1[S2 * OCPAD2 * HW];
__device__ float  g_h [OUTDIM * HW];
__device__ float  g_flat[NROIS * OUTDIM];
__device__ float  g_fc1[NROIS * 2048];

// ---------------- PTX helpers ----------------
__device__ __forceinline__ uint32_t smem_u32(const void* p) {
    uint32_t a;
    asm("{ .reg .u64 t; cvta.to.shared.u64 t, %1; cvt.u32.u64 %0, t; }" : "=r"(a) : "l"(p));
    return a;
}
__device__ __forceinline__ void cp16(uint32_t dst, const __half* src) {
    asm volatile("cp.async.cg.shared.global [%0], [%1], 16;"
                 :: "r"(dst), "l"(__cvta_generic_to_global(src)));
}
__device__ __forceinline__ void cp_commit() { asm volatile("cp.async.commit_group;" ::: "memory"); }
template<int N> __device__ __forceinline__ void cp_wait() {
    asm volatile("cp.async.wait_group %0;" :: "n"(N) : "memory");
}
__device__ __forceinline__ void ldsm4(uint32_t* r, uint32_t addr) {
    asm volatile("ldmatrix.sync.aligned.m8n8.x4.shared.b16 {%0,%1,%2,%3}, [%4];"
        : "=r"(r[0]), "=r"(r[1]), "=r"(r[2]), "=r"(r[3]) : "r"(addr));
}
__device__ __forceinline__ void mma16(float* c, const uint32_t* a, const uint32_t* b) {
    asm volatile("mma.sync.aligned.m16n8k16.row.col.f32.f16.f16.f32 "
        "{%0,%1,%2,%3}, {%4,%5,%6,%7}, {%8,%9}, {%0,%1,%2,%3};"
        : "+f"(c[0]), "+f"(c[1]), "+f"(c[2]), "+f"(c[3])
        : "r"(a[0]), "r"(a[1]), "r"(a[2]), "r"(a[3]), "r"(b[0]), "r"(b[1]));
}
__device__ __forceinline__ void ffma2u(unsigned long long &d, unsigned long long a, unsigned long long b) {
    asm("fma.rn.f32x2 %0, %1, %2, %0;" : "+l"(d) : "l"(a), "l"(b));
}
__device__ __forceinline__ unsigned long long bcast2(float x) {
    unsigned long long r;
    asm("mov.b64 %0, {%1, %1};" : "=l"(r) : "f"(x));
    return r;
}
__device__ __forceinline__ float2 unpack2(unsigned long long v) {
    float2 r;
    asm("mov.b64 {%0, %1}, %2;" : "=f"(r.x), "=f"(r.y) : "l"(v));
    return r;
}

// ---------------- prep ----------------
__global__ void zero_fill(uint4* a, int na, uint4* b, int nb, uint4* c, int nc, uint4* d, int nd) {
    for (int i = blockIdx.x * blockDim.x + threadIdx.x; i < na; i += gridDim.x * blockDim.x) {
        const uint4 z = make_uint4(0, 0, 0, 0);
        a[i] = z; b[i] = z;
        if (i < nc) { c[i] = z; d[i] = z; }
    }
}

__global__ __launch_bounds__(256) void xpose(const float* __restrict__ x,
                                             __half2* __restrict__ XPa, __half2* __restrict__ XPb)
{
    __shared__ float s[64][65];
    const int c0 = blockIdx.x * 64, p0 = blockIdx.y * 64;
    const int tid = threadIdx.x;
    const int r = tid >> 2, q0 = (tid & 3) * 16;
#pragma unroll
    for (int q = 0; q < 16; q++) {
        const int p = p0 + q0 + q;
        s[r][q0 + q] = (p < HW) ? x[(size_t)(c0 + r) * HW + p] : 0.f;
    }
    __syncthreads();
#pragma unroll
    for (int k = 0; k < 8; k++) {
        const int widx = tid + k * 256;
        const int pl = widx >> 5, cp = widx & 31;
        const int p = p0 + pl;
        if (p < HW) {
            const int i = p / FW, j = p - i * FW;
            const __half2 v = __floats2half2_rn(s[2 * cp][pl], s[2 * cp + 1][pl]);
            XPa[(size_t)((i + 7) * 64 + j + 7) * 1024 + (c0 >> 1) + cp] = v;
            XPb[(size_t)((j + 7) * 64 + i + 7) * 1024 + (c0 >> 1) + cp] = v;
        }
    }
}

__global__ __launch_bounds__(256) void wtrans(const float* __restrict__ w, __half* __restrict__ wt,
                                              int OC, int OCpad, int IC)
{
    __shared__ float s[128 * TAPS];
    const int m = blockIdx.x, c0 = blockIdx.y * 128;
    const int tid = threadIdx.x;
    if (m < OC) {
        const float* src = w + ((size_t)m * IC + c0) * TAPS;
        for (int i = tid; i < 128 * TAPS; i += 256) s[i] = src[i];
    } else {
        for (int i = tid; i < 128 * TAPS; i += 256) s[i] = 0.f;
    }
    __syncthreads();
    for (int i = tid; i < 128 * TAPS; i += 256) {
        const int t = i >> 7, ci = i & 127;
        wt[((size_t)t * OCpad + m) * IC + c0 + ci] = __float2half(s[ci * TAPS + t]);
    }
}

// ============ sliding-window tap conv: one B window per channel chunk ============
#define WR 512
#define APITCH 80
#define ABUF (128 * APITCH)                // 10240
#define BBUF (WR * APITCH)                 // 40960
#define CONV_SMEM (2 * ABUF + 2 * BBUF)    // 102400

__global__ __launch_bounds__(256, 1) void conv_mma(
    const __half* __restrict__ inB0, const __half* __restrict__ inB1,
    const __half* __restrict__ wA0,  const __half* __restrict__ wA1,
    float* __restrict__ out0, float* __restrict__ out1,
    int D0, int D1, int ICfull, int icChunks, int OCpad, int S)
{
    extern __shared__ __align__(16) char smem[];
    const int z = blockIdx.z;
    const int br = z / S, s = z % S;
    const __half* inB = br ? inB1 : inB0;
    const __half* wA  = br ? wA1  : wA0;
    const int D = br ? D1 : D0;
    float* out = (br ? out1 : out0) + (size_t)s * OCpad * HW;
    const int m0 = blockIdx.y * 128;
    const int pi0 = blockIdx.x * 256;
    const int icOff = s * icChunks * 32;
    const int nit = icChunks * TAPS;
    const int row0 = (pi0 / D + 7) * 64 + pi0 % D;   // row(pi0)-7

    const int tid = threadIdx.x, lane = tid & 31, wid = tid >> 5;
    const int wm = (wid >> 2) * 64, wn = (wid & 3) * 64;
    const int lg = lane >> 2, lt = lane & 3;
    const uint32_t sb = smem_u32(smem);
    const uint32_t aB[2] = { sb, sb + ABUF };
    const uint32_t bB[2] = { sb + 2 * ABUF, sb + 2 * ABUF + BBUF };

    const int arow = tid >> 1, aseg = tid & 1;
    const __half* aBase = wA + (size_t)(m0 + arow) * ICfull + icOff + aseg * 16;
    const size_t aTap = (size_t)OCpad * ICfull;
    const uint32_t aDst = (uint32_t)(arow * APITCH + aseg * 32);
    const uint32_t aLane = (uint32_t)((wm + (lane & 7) + ((lane >> 3) & 1) * 8) * APITCH + ((lane >> 4) & 1) * 16);

    uint32_t bLaneOff[4];
#pragma unroll
    for (int pr = 0; pr < 4; pr++) {
        const int nl = wn + (lane & 7) + ((lane >> 4) & 1) * 8 + pr * 16;
        int pi = pi0 + nl; if (pi > HW - 1) pi = HW - 1;
        const int rr = (pi / D + 7) * 64 + pi % D + 7 - row0 - 7;   // row(pi)-row(pi0), >=0
        bLaneOff[pr] = (uint32_t)(rr * APITCH + ((lane >> 3) & 1) * 16);
    }

    float acc[4][8][4];
#pragma unroll
    for (int mi = 0; mi < 4; mi++)
#pragma unroll
        for (int ni = 0; ni < 8; ni++)
#pragma unroll
            for (int q = 0; q < 4; q++) acc[mi][ni][q] = 0.f;

    auto issueA = [&](int g) {
        const int t = g % TAPS, c = g / TAPS;
        const __half* aS = aBase + (size_t)t * aTap + c * 32;
        const uint32_t d = aB[g & 1] + aDst;
        cp16(d, aS); cp16(d + 16, aS + 8);
    };
    auto issueBwin = [&](int c) {
        const uint32_t bb = bB[c & 1];
#pragma unroll
        for (int r = 0; r < 2; r++) {
            const int wr = tid + r * 256;
            int grow = row0 + wr; if (grow > PROWS - 1) grow = PROWS - 1;
            const __half* src = inB + (size_t)grow * ICfull + icOff + c * 32;
            const uint32_t d = bb + wr * APITCH;
            cp16(d, src); cp16(d + 16, src + 8); cp16(d + 32, src + 16); cp16(d + 48, src + 24);
        }
    };

    issueA(0); issueBwin(0); cp_commit();

    int tCur = 0, cCur = 0;
    for (int g = 0; g < nit; ++g) {
        if (g + 1 < nit) {
            issueA(g + 1);
            if ((g + 1) % TAPS == 0) issueBwin((g + 1) / TAPS);
        }
        cp_commit();
        cp_wait<1>();
        __syncthreads();

        const uint32_t abuf = aB[g & 1];
        const uint32_t bbuf = bB[cCur & 1] + tCur * APITCH;
#pragma unroll
        for (int ks = 0; ks < 2; ks++) {
            uint32_t af[4][4], bf[8][2];
#pragma unroll
            for (int mi = 0; mi < 4; mi++)
                ldsm4(af[mi], abuf + aLane + mi * (16 * APITCH) + ks * 32);
#pragma unroll
            for (int pr = 0; pr < 4; pr++) {
                uint32_t r[4];
                ldsm4(r, bbuf + bLaneOff[pr] + ks * 32);
                bf[pr * 2][0] = r[0]; bf[pr * 2][1] = r[1];
                bf[pr * 2 + 1][0] = r[2]; bf[pr * 2 + 1][1] = r[3];
            }
#pragma unroll
            for (int mi = 0; mi < 4; mi++)
#pragma unroll
                for (int ni = 0; ni < 8; ni++)
                    mma16(acc[mi][ni], af[mi], bf[ni]);
        }
        __syncthreads();
        if (++tCur == TAPS) { tCur = 0; cCur++; }
    }

#pragma unroll
    for (int mi = 0; mi < 4; mi++) {
        const int r0 = m0 + wm + mi * 16 + lg;
#pragma unroll
        for (int ni = 0; ni < 8; ni++) {
            const int cc = pi0 + wn + ni * 8 + 2 * lt;
            if (cc < HW) {
                *(float2*)&out[(size_t)r0 * HW + cc] = make_float2(acc[mi][ni][0], acc[mi][ni][1]);
                *(float2*)&out[(size_t)(r0 + 8) * HW + cc] = make_float2(acc[mi][ni][2], acc[mi][ni][3]);
            }
        }
    }
}

// ---------------- combine1: sum splits + bias -> padded half conv2 inputs ----------------
// b=0: src enum e=j*38+i (j-major) -> TP0 i-major. b=1: src enum p (i-major) -> TP1 j-major.
__global__ __launch_bounds__(256) void combine1(const float* __restrict__ p1,
                                                const float* __restrict__ b0, const float* __restrict__ b1,
                                                __half2* __restrict__ TP0, __half2* __restrict__ TP1)
{
    __shared__ float s[64][65];
    const int b = blockIdx.z;
    const int m0 = blockIdx.x * 64, e0 = blockIdx.y * 64;
    const int tid = threadIdx.x;
    const float* src = p1 + (size_t)b * S1 * OCPAD1 * HW;
    const int r = tid >> 2, q0 = (tid & 3) * 16;
#pragma unroll
    for (int q = 0; q < 16; q++) {
        const int e = e0 + q0 + q;
        float v = 0.f;
        if (e < HW) {
#pragma unroll
            for (int ss = 0; ss < S1; ss++)
                v += src[((size_t)ss * OCPAD1 + m0 + r) * HW + e];
        }
        s[r][q0 + q] = v;
    }
    __syncthreads();
    const float* bias = b ? b1 : b0;
    __half2* TP = b ? TP1 : TP0;
#pragma unroll
    for (int k = 0; k < 8; k++) {
        const int widx = tid + k * 256;
        const int pl = widx >> 5, cp = widx & 31;
        const int e = e0 + pl;
        if (e < HW) {
            int row;
            if (b == 0) { const int i = e % 38, j = e / 38; row = (i + 7) * 64 + j + 7; }
            else        { const int i = e / 50, j = e % 50; row = (j + 7) * 64 + i + 7; }
            const float vx = s[2 * cp][pl] + bias[m0 + 2 * cp];
            const float vy = s[2 * cp + 1][pl] + bias[m0 + 2 * cp + 1];
            TP[(size_t)row * 128 + (m0 >> 1) + cp] = __floats2half2_rn(vx, vy);
        }
    }
}

// ---------------- combine2: h0 natural p, h1 enum e=(p%50)*38+p/50 ----------------
__global__ void combine2(const float* __restrict__ h0, const float* __restrict__ h1,
                         const float* __restrict__ bc, const float* __restrict__ brr,
                         float* __restrict__ h)
{
    const int idx = blockIdx.x * blockDim.x + threadIdx.x;
    if (idx >= OUTDIM * HW) return;
    const int ch = idx / HW, p = idx - ch * HW;
    const int e = (p % 50) * 38 + p / 50;
    float v = bc[ch] + brr[ch];
#pragma unroll
    for (int ss = 0; ss < S2; ss++) {
        v += h0[((size_t)ss * OCPAD2 + ch) * HW + p];
        v += h1[((size_t)ss * OCPAD2 + ch) * HW + e];
    }
    h[idx] = fmaxf(v, 0.f);
}

// ---------------- ROI bilinear max pool ----------------
__global__ void roi_pool(const float* __restrict__ h, const float* __restrict__ rois,
                         float* __restrict__ flat)
{
    const int idx = blockIdx.x * blockDim.x + threadIdx.x;
    if (idx >= NROIS * OUTDIM) return;
    const int n  = idx / OUTDIM;
    const int ch = idx - n * OUTDIM;
    const int bin = ch / 10;
    const int bi  = bin / 7;
    const int bj  = bin - bi * 7;

    const float4 r = ((const float4*)rois)[n];
    const float xmin = (r.x * 0.0625f) / 50.f;
    const float ymin = (r.y * 0.0625f) / 38.f;
    const float xmax = (r.z * 0.0625f) / 50.f;
    const float ymax = (r.w * 0.0625f) / 38.f;
    const float stx = (xmax - xmin) / 7.f;
    const float sty = (ymax - ymin) / 7.f;

    const float* f = h + (size_t)ch * HW;
    float best = -3.4e38f;
#pragma unroll
    for (int ky = 0; ky < 2; ky++) {
        const float yy = (ymin + (float)(bi + ky) * sty) * 37.f;
        const float fy = floorf(yy);
        const float wy = yy - fy;
        const int y0 = (int)fminf(fmaxf(fy, 0.f), 37.f);
        const int y1 = (int)fminf(fmaxf(fy + 1.f, 0.f), 37.f);
#pragma unroll
        for (int kx = 0; kx < 2; kx++) {
            const float xx = (xmin + (float)(bj + kx) * stx) * 49.f;
            const float fx = floorf(xx);
            const float wx = xx - fx;
            const int x0 = (int)fminf(fmaxf(fx, 0.f), 49.f);
            const int x1 = (int)fminf(fmaxf(fx + 1.f, 0.f), 49.f);
            const float v00 = f[y0 * FW + x0];
            const float v01 = f[y0 * FW + x1];
            const float v10 = f[y1 * FW + x0];
            const float v11 = f[y1 * FW + x1];
            const float top = v00 + (v01 - v00) * wx;
            const float bot = v10 + (v11 - v10) * wx;
            const float val = top + (bot - top) * wy;
            best = fmaxf(best, val);
        }
    }
    flat[idx] = best;
}

// ---------------- GEMM: C = A * B^T + bias ----------------
#define GBM 64
#define GBN 64
#define GBK 16

__global__ __launch_bounds__(128, 1) void gemm_tn(
    const float* __restrict__ A, const float* __restrict__ B,
    const float* __restrict__ bias, float* __restrict__ C,
    int M, int N, int K, int ldc, int relu)
{
    const int m0 = blockIdx.y * GBM;
    const int n0 = blockIdx.x * GBN;
    const int nit = (K + GBK - 1) / GBK;

    __shared__ __align__(16) float As[GBK][GBM + 4];
    __shared__ __align__(16) float Bs[GBK][GBN + 4];

    const int tid = threadIdx.x;
    const int tx = tid & 15;
    const int ty = tid >> 4;
    const int lr  = tid >> 1;
    const int lkq = (tid & 1) * 8;

    unsigned long long acc[8][2];
#pragma unroll
    for (int i = 0; i < 8; i++) { acc[i][0] = 0ull; acc[i][1] = 0ull; }

    for (int it = 0; it < nit; ++it) {
        const int k0 = it * GBK;
        {
            const int m = m0 + lr;
            const float* p = A + (size_t)m * K + k0 + lkq;
#pragma unroll
            for (int q = 0; q < 8; q++) {
                const int k = k0 + lkq + q;
                As[lkq + q][lr] = (m < M && k < K) ? __ldg(p + q) : 0.f;
            }
        }
        {
            const int nn = n0 + lr;
            const float* p = B + (size_t)nn * K + k0 + lkq;
#pragma unroll
            for (int q = 0; q < 8; q++) {
                const int k = k0 + lkq + q;
                Bs[lkq + q][lr] = (nn < N && k < K) ? __ldg(p + q) : 0.f;
            }
        }
        __syncthreads();
#pragma unroll
        for (int kk = 0; kk < GBK; kk++) {
            const float4 a0 = *(const float4*)&As[kk][ty * 8];
            const float4 a1 = *(const float4*)&As[kk][ty * 8 + 4];
            const ulonglong2 bv = *(const ulonglong2*)&Bs[kk][tx * 4];
            const float a[8] = { a0.x, a0.y, a0.z, a0.w, a1.x, a1.y, a1.z, a1.w };
#pragma unroll
            for (int mi = 0; mi < 8; mi++) {
                const unsigned long long av = bcast2(a[mi]);
                ffma2u(acc[mi][0], av, bv.x);
                ffma2u(acc[mi][1], av, bv.y);
            }
        }
        __syncthreads();
    }

#pragma unroll
    for (int mi = 0; mi < 8; mi++) {
        const int m = m0 + ty * 8 + mi;
        if (m >= M) continue;
        float* crow = C + (size_t)m * ldc;
#pragma unroll
        for (int nj = 0; nj < 2; nj++) {
            const float2 v = unpack2(acc[mi][nj]);
            const int n = n0 + tx * 4 + nj * 2;
            if (n < N) {
                float o = v.x + bias[n];
                if (relu) o = o > 0.f ? o : 0.f;
                crow[n] = o;
            }
            if (n + 1 < N) {
                float o = v.y + bias[n + 1];
                if (relu) o = o > 0.f ? o : 0.f;
                crow[n + 1] = o;
            }
        }
    }
}

// ---------------- launch ----------------
extern "C" void kernel_launch(void* const* d_in, const int* in_sizes, int n_in,
                              void* d_out, int out_size)
{
    const float* x          = (const float*)d_in[0];
    const float* rois       = (const float*)d_in[1];
    const float* w_col_max  = (const float*)d_in[2];
    const float* b_col_max  = (const float*)d_in[3];
    const float* w_col      = (const float*)d_in[4];
    const float* b_col      = (const float*)d_in[5];
    const float* w_row_max  = (const float*)d_in[6];
    const float* b_row_max  = (const float*)d_in[7];
    const float* w_row      = (const float*)d_in[8];
    const float* b_row      = (const float*)d_in[9];
    const float* w_fc1      = (const float*)d_in[10];
    const float* b_fc1      = (const float*)d_in[11];
    const float* w_score    = (const float*)d_in[12];
    const float* b_score    = (const float*)d_in[13];
    const float* w_loc      = (const float*)d_in[14];
    const float* b_loc      = (const float*)d_in[15];
    float* out = (float*)d_out;

    __half *XPa, *XPb, *TP0, *TP1, *wt1, *wt2;
    float *p1, *h0, *h1, *h, *flat, *fc1;
    cudaGetSymbolAddress((void**)&XPa,  g_XPa);
    cudaGetSymbolAddress((void**)&XPb,  g_XPb);
    cudaGetSymbolAddress((void**)&TP0,  g_TP0);
    cudaGetSymbolAddress((void**)&TP1,  g_TP1);
    cudaGetSymbolAddress((void**)&wt1,  g_wt1);
    cudaGetSymbolAddress((void**)&wt2,  g_wt2);
    cudaGetSymbolAddress((void**)&p1,   g_p1);
    cudaGetSymbolAddress((void**)&h0,   g_h0);
    cudaGetSymbolAddress((void**)&h1,   g_h1);
    cudaGetSymbolAddress((void**)&h,    g_h);
    cudaGetSymbolAddress((void**)&flat, g_flat);
    cudaGetSymbolAddress((void**)&fc1,  g_fc1);

    cudaFuncSetAttribute(conv_mma, cudaFuncAttributeMaxDynamicSharedMemorySize, CONV_SMEM);

    {
        const int na = PROWS * 2048 * 2 / 16;   // per XP buffer
        const int nc = PROWS * 256  * 2 / 16;   // per TP buffer
        zero_fill<<<4096, 256>>>((uint4*)XPa, na, (uint4*)XPb, na, (uint4*)TP0, nc, (uint4*)TP1, nc);
    }
    xpose<<<dim3(2048 / 64, (HW + 63) / 64), 256>>>(x, (__half2*)XPa, (__half2*)XPb);
    wtrans<<<dim3(OCPAD1, 2048 / 128), 256>>>(w_col_max, wt1, 256, OCPAD1, 2048);
    wtrans<<<dim3(OCPAD1, 2048 / 128), 256>>>(w_row_max, wt1 + (size_t)TAPS * OCPAD1 * 2048, 256, OCPAD1, 2048);
    wtrans<<<dim3(OCPAD2, 256 / 128), 256>>>(w_col, wt2, OUTDIM, OCPAD2, 256);
    wtrans<<<dim3(OCPAD2, 256 / 128), 256>>>(w_row, wt2 + (size_t)TAPS * OCPAD2 * 256, OUTDIM, OCPAD2, 256);

    // conv1: br0 = w_col_max (H-shift) on j-major XPb (D=38); br1 = w_row_max (W-shift) on i-major XPa (D=50)
    {
        dim3 grid(8, OCPAD1 / 128, 2 * S1);   // 8 x 2 x 8 = 128
        conv_mma<<<grid, 256, CONV_SMEM>>>(
            XPb, XPa,
            wt1, wt1 + (size_t)TAPS * OCPAD1 * 2048,
            p1, p1 + (size_t)S1 * OCPAD1 * HW,
            38, 50, 2048, 2048 / 32 / S1, OCPAD1, S1);
    }
    combine1<<<dim3(OCPAD1 / 64, (HW + 63) / 64, 2), 256>>>(p1, b_col_max, b_row_max,
                                                            (__half2*)TP0, (__half2*)TP1);
    // conv2: br0 = w_col (W-shift) on i-major TP0 (D=50); br1 = w_row (H-shift) on j-major TP1 (D=38)
    {
        dim3 grid(8, OCPAD2 / 128, 2 * S2);   // 8 x 4 x 4 = 128
        conv_mma<<<grid, 256, CONV_SMEM>>>(
            TP0, TP1,
            wt2, wt2 + (size_t)TAPS * OCPAD2 * 256,
            h0, h1,
            50, 38, 256, 256 / 32 / S2, OCPAD2, S2);
    }
    {
        const int n = OUTDIM * HW;
        combine2<<<(n + 255) / 256, 256>>>(h0, h1, b_col, b_row, h);
    }
    {
        const int n = NROIS * OUTDIM;
        roi_pool<<<(n + 255) / 256, 256>>>(h, rois, flat);
    }
    {
        dim3 grid(2048 / GBN, NROIS / GBM);
        gemm_tn<<<grid, 128>>>(flat, w_fc1, b_fc1, fc1, NROIS, 2048, OUTDIM, 2048, 1);
    }
    {
        dim3 grid((324 + GBN - 1) / GBN, NROIS / GBM);
        gemm_tn<<<grid, 128>>>(fc1, w_loc, b_loc, out, NROIS, 324, 2048, 324, 0);
    }
    {
        dim3 grid((81 + GBN - 1) / GBN, NROIS / GBM);
        gemm_tn<<<grid, 128>>>(fc1, w_score, b_score, out + NROIS * 324, NROIS, 81, 2048, 81, 0);
    }
}